// round 6
// baseline (speedup 1.0000x reference)
#include <cuda_runtime.h>
#include <cuda_fp16.h>
#include <cstdint>

#define Tn 17
#define Bn 4096
#define Cn 512
#define Dn 512
#define Kn 1024
#define TILE_M 128
#define TILE_N 256
#define NSTAGE 16        // K stages per tile (64 elems = 128B each)
#define PIPE 4
#define NTILES 1088      // 17 * 32 * 2

// -------------------- scratch ------------------------------------------------
__device__ __align__(256) __half g_A[(size_t)Tn * Bn * Kn];  // ~143 MB
__device__ __align__(256) __half g_W[(size_t)Tn * Dn * Kn];  // ~18 MB
__device__ float g_bias[Tn * Dn];

// -------------------- helpers ------------------------------------------------
__device__ __forceinline__ uint32_t smem_u32(const void* p) {
    uint32_t a;
    asm("{ .reg .u64 t; cvta.to.shared.u64 t, %1; cvt.u32.u64 %0, t; }"
        : "=r"(a) : "l"(p));
    return a;
}

#define SWZ(o) ((o) ^ (((o) >> 3) & 0x70))

#define CP16(smem_addr, gptr) \
    asm volatile("cp.async.cg.shared.global [%0], [%1], 16;" \
                 :: "r"((uint32_t)(smem_addr)), "l"(gptr) : "memory")
#define CP_COMMIT()  asm volatile("cp.async.commit_group;" ::: "memory")
#define CP_WAIT_2()  asm volatile("cp.async.wait_group 2;" ::: "memory")

__device__ __forceinline__ void ldsm4(uint32_t* r, uint32_t addr) {
    asm volatile("ldmatrix.sync.aligned.m8n8.x4.shared.b16 {%0,%1,%2,%3}, [%4];"
                 : "=r"(r[0]), "=r"(r[1]), "=r"(r[2]), "=r"(r[3]) : "r"(addr));
}

__device__ __forceinline__ void mma16816(float* c, const uint32_t* a,
                                         uint32_t b0, uint32_t b1) {
    asm volatile(
        "mma.sync.aligned.m16n8k16.row.col.f32.f16.f16.f32 "
        "{%0,%1,%2,%3}, {%4,%5,%6,%7}, {%8,%9}, {%0,%1,%2,%3};"
        : "+f"(c[0]), "+f"(c[1]), "+f"(c[2]), "+f"(c[3])
        : "r"(a[0]), "r"(a[1]), "r"(a[2]), "r"(a[3]), "r"(b0), "r"(b1));
}

#define STAGE_BYTES 49152u            // A 16K + B 32K
#define SMEM_TOTAL  (PIPE * STAGE_BYTES)

// tile decode: tau -> byte offsets into g_A / g_W (both fit in 32 bits)
__device__ __forceinline__ void tile_rows(int tau, uint32_t& rA, uint32_t& rB,
                                          int& t, int& bm, int& bn) {
    t  = tau >> 6;
    const int rem = tau & 63;
    bm = rem >> 1;
    bn = rem & 1;
    rA = (uint32_t)(t * Bn + bm * TILE_M) * (Kn * 2);
    rB = (uint32_t)(t * Dn + bn * TILE_N) * (Kn * 2);
}

// -------------------- prep: seasonal/trend -> fp16 ---------------------------
__device__ __forceinline__ void write_h(__half* ph, float4 v) {
    float a[4] = {v.x, v.y, v.z, v.w};
    uint2 uh;
    unsigned short h[4];
#pragma unroll
    for (int i = 0; i < 4; ++i) h[i] = __half_as_ushort(__float2half_rn(a[i]));
    uh.x = (uint32_t)h[0] | ((uint32_t)h[1] << 16);
    uh.y = (uint32_t)h[2] | ((uint32_t)h[3] << 16);
    *reinterpret_cast<uint2*>(ph) = uh;
}

__global__ void prep_kernel(const float* __restrict__ x) {
    const int b  = blockIdx.x;
    const int c4 = threadIdx.x;
    const float4* xb = reinterpret_cast<const float4*>(x) + (size_t)b * (Tn * Cn / 4);

    float4 v[Tn];
    float sx = 0.f, sy = 0.f, sz = 0.f, sw = 0.f;
#pragma unroll
    for (int t = 0; t < Tn; ++t) {
        v[t] = xb[t * (Cn / 4) + c4];
        sx += v[t].x; sy += v[t].y; sz += v[t].z; sw += v[t].w;
    }
    const float4 x0 = v[0];
    const float4 xl = v[Tn - 1];
    const float inv = 1.0f / 37.0f;

#pragma unroll
    for (int t = 0; t < Tn; ++t) {
        const float a = (float)(18 - t);
        const float c = (float)(t + 2);
        float4 tr, se;
        tr.x = (sx + a * x0.x + c * xl.x) * inv;
        tr.y = (sy + a * x0.y + c * xl.y) * inv;
        tr.z = (sz + a * x0.z + c * xl.z) * inv;
        tr.w = (sw + a * x0.w + c * xl.w) * inv;
        se.x = v[t].x - tr.x; se.y = v[t].y - tr.y;
        se.z = v[t].z - tr.z; se.w = v[t].w - tr.w;
        const size_t row = ((size_t)t * Bn + b) * Kn;
        write_h(g_A + row + c4 * 4,       se);
        write_h(g_A + row + 512 + c4 * 4, tr);
    }
}

__global__ void wprep_kernel(const float* __restrict__ Ws, const float* __restrict__ Wt,
                             const float* __restrict__ bs, const float* __restrict__ bt) {
    const size_t gid = (size_t)blockIdx.x * blockDim.x + threadIdx.x;
    const size_t total = (size_t)Tn * Dn * (Cn / 4);
    if (gid < total) {
        const size_t row = gid >> 7;
        const int    c4  = (int)(gid & 127);
        float4 s = reinterpret_cast<const float4*>(Ws)[row * 128 + c4];
        float4 t = reinterpret_cast<const float4*>(Wt)[row * 128 + c4];
        const size_t wrow = row * Kn;
        write_h(g_W + wrow + c4 * 4,       s);
        write_h(g_W + wrow + 512 + c4 * 4, t);
    }
    if (gid < (size_t)Tn * Dn) g_bias[gid] = bs[gid] + bt[gid];
}

// -------------------- persistent grouped GEMM -------------------------------
__device__ __forceinline__ void load_stage(int ks, uint32_t buf_base, int tid,
                                           uint32_t rA, uint32_t rB) {
    const uint32_t colByte = (uint32_t)ks * 128u;
    const char* gA = (const char*)g_A;
    const char* gW = (const char*)g_W;
#pragma unroll
    for (int i = 0; i < 2; ++i) {           // A: 1024 lines / 512 thr
        const int idx = tid + i * 512;
        const int r = idx >> 3;
        const int cb = (idx & 7) * 16;
        const uint32_t sw = SWZ((uint32_t)(r * 128 + cb));
        CP16(buf_base + sw, gA + rA + (uint32_t)r * (Kn * 2) + colByte + cb);
    }
#pragma unroll
    for (int i = 0; i < 4; ++i) {           // B: 2048 lines / 512 thr
        const int idx = tid + i * 512;
        const int r = idx >> 3;
        const int cb = (idx & 7) * 16;
        const uint32_t sw = SWZ((uint32_t)(r * 128 + cb));
        CP16(buf_base + 16384u + sw, gW + rB + (uint32_t)r * (Kn * 2) + colByte + cb);
    }
}

__global__ __launch_bounds__(512, 1) void gemm_kernel(float* __restrict__ out) {
    extern __shared__ char smem[];
    const uint32_t sb = smem_u32(smem);
    const int tid = threadIdx.x, wid = tid >> 5, lane = tid & 31;

    const int wm = wid & 3;
    const int wn = wid >> 2;
    const int mbase = wm * 32;
    const int nbase = wn * 64;

    const int tid8 = lane >> 3;
    const int r8   = lane & 7;
    const int rowOff = ((tid8 & 1) << 3) + r8;
    const int colOff = (tid8 >> 1) << 4;

    // hoisted swizzle: SWZ(row*128 + k) = row*128 + (k ^ xorpat), k < 128
    uint32_t aRow[2], aXor[2], bRow[4], bXor[4];
#pragma unroll
    for (int mf = 0; mf < 2; ++mf) {
        aRow[mf] = (uint32_t)(mbase + mf * 16 + rowOff) * 128u;
        aXor[mf] = (aRow[mf] >> 3) & 0x70u;
    }
#pragma unroll
    for (int g = 0; g < 4; ++g) {
        bRow[g] = (uint32_t)(nbase + g * 16 + rowOff) * 128u + 16384u;
        bXor[g] = (((uint32_t)(nbase + g * 16 + rowOff) * 128u) >> 3) & 0x70u;
    }

    // load cursor (3 stages ahead of compute)
    int tauL = blockIdx.x, ksL = 0;
    uint32_t rA_L, rB_L; int tL, bmL, bnL;
    tile_rows(tauL, rA_L, rB_L, tL, bmL, bnL);

    int bufC = 0;  // compute buffer index (cycles 0..3)

    // prologue: stages 0..2 of first tile
#pragma unroll
    for (int i = 0; i < 3; ++i) {
        load_stage(ksL, sb + (uint32_t)i * STAGE_BYTES, tid, rA_L, rB_L);
        CP_COMMIT();
        ++ksL;
    }
    int bufL = 3;  // next load buffer

    float acc[2][8][4];
#pragma unroll
    for (int i = 0; i < 2; ++i)
#pragma unroll
        for (int j = 0; j < 8; ++j)
#pragma unroll
            for (int q = 0; q < 4; ++q) acc[i][j][q] = 0.f;

    for (int tauC = blockIdx.x; tauC < NTILES; tauC += gridDim.x) {
        int tC, bmC, bnC; uint32_t rA_C, rB_C;
        tile_rows(tauC, rA_C, rB_C, tC, bmC, bnC);

        for (int ks = 0; ks < NSTAGE; ++ks) {
            CP_WAIT_2();
            __syncthreads();

            // issue load 3 stages ahead (or empty commit at the very end)
            if (tauL < NTILES) {
                load_stage(ksL, sb + (uint32_t)bufL * STAGE_BYTES, tid, rA_L, rB_L);
                if (++ksL == NSTAGE) {
                    ksL = 0;
                    tauL += gridDim.x;
                    if (tauL < NTILES) tile_rows(tauL, rA_L, rB_L, tL, bmL, bnL);
                }
            }
            CP_COMMIT();
            bufL = (bufL + 1) & 3;

            const uint32_t st = sb + (uint32_t)bufC * STAGE_BYTES;
            bufC = (bufC + 1) & 3;

#pragma unroll
            for (int kk = 0; kk < 4; ++kk) {
                const uint32_t kcb = (uint32_t)(kk * 32 + colOff);
                uint32_t ah[2][4], bh[4][4];
#pragma unroll
                for (int mf = 0; mf < 2; ++mf)
                    ldsm4(ah[mf], st + aRow[mf] + (kcb ^ aXor[mf]));
#pragma unroll
                for (int g = 0; g < 4; ++g)
                    ldsm4(bh[g], st + bRow[g] + (kcb ^ bXor[g]));
#pragma unroll
                for (int mf = 0; mf < 2; ++mf)
#pragma unroll
                    for (int g = 0; g < 4; ++g) {
                        mma16816(acc[mf][g * 2 + 0], ah[mf], bh[g][0], bh[g][2]);
                        mma16816(acc[mf][g * 2 + 1], ah[mf], bh[g][1], bh[g][3]);
                    }
            }
        }

        // ---------------- epilogue (overlaps with in-flight loads) ----------
        const int qrow = lane >> 2;
        const int qcol = (lane & 3) * 2;
        char* outc = (char*)out;
#pragma unroll
        for (int mf = 0; mf < 2; ++mf) {
            const uint32_t row0 = (uint32_t)(bmC * TILE_M + mbase + mf * 16 + qrow);
#pragma unroll
            for (int nf = 0; nf < 8; ++nf) {
                const int col = bnC * TILE_N + nbase + nf * 8 + qcol;
                const float2 bv = *reinterpret_cast<const float2*>(g_bias + tC * Dn + col);
                float2 o0, o1;
                o0.x = acc[mf][nf][0] + bv.x;
                o0.y = acc[mf][nf][1] + bv.y;
                o1.x = acc[mf][nf][2] + bv.x;
                o1.y = acc[mf][nf][3] + bv.y;
                const uint32_t base = (row0 * (Tn * Dn) + (uint32_t)tC * Dn + (uint32_t)col) * 4u;
                *reinterpret_cast<float2*>(outc + base) = o0;
                *reinterpret_cast<float2*>(outc + base + (uint32_t)(8 * Tn * Dn * 4)) = o1;
                acc[mf][nf][0] = 0.f; acc[mf][nf][1] = 0.f;
                acc[mf][nf][2] = 0.f; acc[mf][nf][3] = 0.f;
            }
        }
    }
}

// ---------------------------------------------------------------------------
extern "C" void kernel_launch(void* const* d_in, const int* in_sizes, int n_in,
                              void* d_out, int out_size) {
    const float* x  = (const float*)d_in[0];
    const float* Ws = (const float*)d_in[1];
    const float* bs = (const float*)d_in[2];
    const float* Wt = (const float*)d_in[3];
    const float* bt = (const float*)d_in[4];
    float* out = (float*)d_out;

    cudaFuncSetAttribute(gemm_kernel, cudaFuncAttributeMaxDynamicSharedMemorySize, SMEM_TOTAL);

    prep_kernel<<<Bn, 128>>>(x);

    const size_t wtotal = (size_t)Tn * Dn * (Cn / 4);
    wprep_kernel<<<(unsigned)((wtotal + 255) / 256), 256>>>(Ws, Wt, bs, bt);

    gemm_kernel<<<148, 512, SMEM_TOTAL>>>(out);
}